// round 14
// baseline (speedup 1.0000x reference)
#include <cuda_runtime.h>
#include <cuda_bf16.h>

// Problem constants
#define BATCH 4
#define CIN   64
#define HH    128
#define WW    128
#define OUTC  64
#define K2N   9
#define NPOS  (BATCH*HH*WW)

// Scratch (device globals; no allocation allowed)
__device__ __align__(16) float g_xT[BATCH*HH*WW*CIN];   // [b][y][x][c]
__device__ __align__(16) float g_postT[28*NPOS];        // [j][pos] offsets/masks (transposed)
__device__ __align__(16) float g_cwT[9*64*28];          // [tap][c][j]
__device__ __align__(16) float g_dwT[9*64*64];          // [k][c][o]

// ------------------------- f32x2 helpers (sm_100+) -------------------------
__device__ __forceinline__ void ffma2(unsigned long long& d,
                                      unsigned long long a,
                                      unsigned long long b) {
    asm("fma.rn.f32x2 %0, %1, %2, %0;" : "+l"(d) : "l"(a), "l"(b));
}
__device__ __forceinline__ unsigned long long dup2(float a) {
    unsigned long long r;
    asm("mov.b64 %0, {%1, %1};" : "=l"(r) : "f"(a));
    return r;
}

// ---------------------------------------------------------------------------
// Kernel W: weight transposes (tiny)
// ---------------------------------------------------------------------------
__global__ void kW(const float* __restrict__ ow, const float* __restrict__ mw,
                   const float* __restrict__ dw) {
    int i = blockIdx.x * blockDim.x + threadIdx.x;
    int stride = gridDim.x * blockDim.x;
    for (int idx = i; idx < 9*64*28; idx += stride) {
        int j   = idx % 28;
        int c   = (idx / 28) % 64;
        int tap = idx / (28*64);
        float v = 0.f;
        if (j < 18)      v = ow[j*576 + c*9 + tap];
        else if (j < 27) v = mw[(j-18)*576 + c*9 + tap];
        g_cwT[idx] = v;
    }
    // g_dwT[k][c][o] = dw[o][c][k]
    for (int idx = i; idx < 9*64*64; idx += stride) {
        int o = idx & 63;
        int c = (idx >> 6) & 63;
        int k = idx >> 12;
        g_dwT[idx] = dw[o*576 + c*9 + k];
    }
}

// ---------------------------------------------------------------------------
// Kernel A: NCHW -> NHWC transpose of x  (grid = BATCH*HH, block = 128)
// ---------------------------------------------------------------------------
__global__ __launch_bounds__(128) void kA(const float* __restrict__ x) {
    int by = blockIdx.x;
    int b = by >> 7, y = by & 127;
    int xq = threadIdx.x;
    const float* src = x + ((size_t)(b*CIN)*HH + y) * WW + xq;
    float* dst = g_xT + (((size_t)b*HH + y) * WW + xq) * CIN;
#pragma unroll
    for (int c4 = 0; c4 < 16; ++c4) {
        float4 v;
        v.x = src[(size_t)(c4*4+0)*HH*WW];
        v.y = src[(size_t)(c4*4+1)*HH*WW];
        v.z = src[(size_t)(c4*4+2)*HH*WW];
        v.w = src[(size_t)(c4*4+3)*HH*WW];
        *reinterpret_cast<float4*>(dst + c4*4) = v;
    }
}

// ---------------------------------------------------------------------------
// Kernel F: FUSED offset/mask conv + bilinear sampling + deform GEMM.
// grid = BATCH*HH, block = 128, __launch_bounds__(128, 4):
//   forces regs <= 128 so 4 blocks/SM are resident -> 592 block capacity
//   >= 512 grid -> SINGLE WAVE (kills the 68-block second-wave tail).
// Smem: A_sh [64][128] (32KB) + W_sh [64][64] (16KB) = 48KB (4/SM ok).
// ---------------------------------------------------------------------------
__global__ __launch_bounds__(128, 4) void kF(const float* __restrict__ x,
                                             const float* __restrict__ ob,
                                             const float* __restrict__ mb,
                                             const float* __restrict__ db,
                                             float* __restrict__ out) {
    __shared__ __align__(16) float A_sh[64][128];
    __shared__ __align__(16) float W_sh[64][64];   // phase2: [c][o]; phase1: cw scratch

    int by = blockIdx.x;
    int b = by >> 7, y = by & 127;
    int tid  = threadIdx.x;
    int lane = tid & 31;
    int warp = tid >> 5;
    size_t rowbase = ((size_t)(b*HH) + y) * WW;   // position index base
    size_t pos = rowbase + tid;

    // ================= Phase 1: offset + mask conv =================
    {
        float* sw = &W_sh[0][0];   // 1792 floats used of 4096
        unsigned long long bacc[14];
#pragma unroll
        for (int j = 0; j < 14; ++j) bacc[j] = 0ULL;

        for (int tap = 0; tap < 9; ++tap) {
            __syncthreads();
            for (int t = tid; t < 448; t += 128)
                reinterpret_cast<float4*>(sw)[t] =
                    reinterpret_cast<const float4*>(g_cwT + tap*1792)[t];
            __syncthreads();

            int ky = tap / 3, kx = tap % 3;
            int ys = y + ky - 1, xs = tid + kx - 1;
            if (ys < 0 || ys > 127 || xs < 0 || xs > 127) continue;  // zero pad

            const float* xc = x + ((size_t)(b*CIN)*HH + ys) * WW + xs;
#pragma unroll 4
            for (int c = 0; c < 64; ++c) {
                unsigned long long ad = dup2(xc[(size_t)c*HH*WW]);
                const float4* wp = reinterpret_cast<const float4*>(sw + c*28);
#pragma unroll
                for (int j4 = 0; j4 < 7; ++j4) {
                    float4 w = wp[j4];
                    const unsigned long long* wu =
                        reinterpret_cast<const unsigned long long*>(&w);
                    ffma2(bacc[j4*2+0], ad, wu[0]);
                    ffma2(bacc[j4*2+1], ad, wu[1]);
                }
            }
        }

        float r[28];
#pragma unroll
        for (int j2 = 0; j2 < 14; ++j2) {
            float2 f = *reinterpret_cast<float2*>(&bacc[j2]);
            r[2*j2+0] = f.x;
            r[2*j2+1] = f.y;
        }
#pragma unroll
        for (int j = 0; j < 18; ++j) r[j] += ob[j];
#pragma unroll
        for (int j = 0; j < 9; ++j) {
            float t = r[18+j] + mb[j];
            r[18+j] = 1.f / (1.f + __expf(-t));
        }
#pragma unroll
        for (int j = 0; j < 27; ++j)
            g_postT[(size_t)j*NPOS + pos] = r[j];
        // block-wide visibility via the __syncthreads() in the k-loop below.
    }

    // ================= Phase 2: sampling + deform GEMM =================
    int pcol = tid & 15;     // GEMM: x pairs at pcol*2 + i2*32
    int og   = tid >> 4;     // GEMM: outputs o = og*8 + j
    int sub  = lane >> 4;    // sampling: position sub-slot (0/1)
    int c4   = lane & 15;    // sampling: channel quad

    unsigned long long acc[32];
#pragma unroll
    for (int j = 0; j < 8; ++j) {
        unsigned long long bd = dup2(db[og*8 + j]);
#pragma unroll
        for (int i2 = 0; i2 < 4; ++i2) acc[i2*8+j] = bd;
    }

    // 32-bit base offset of this image in g_xT (fits: 16M floats)
    int imgbase = (b*HH) * (WW*CIN);

    for (int k = 0; k < 9; ++k) {
        __syncthreads();  // prev GEMM done reading A/W; phase-1 postT visible

        // ---- fill W slab for this k: 1024 float4, 8 per thread ----
        {
            const float4* src = reinterpret_cast<const float4*>(g_dwT + (size_t)k*4096);
            float4* dst = reinterpret_cast<float4*>(&W_sh[0][0]);
#pragma unroll
            for (int t = 0; t < 8; ++t)
                dst[tid + t*128] = src[tid + t*128];
        }

        // ---- per-thread offset scalars for position tid (L1-hot) ----
        float my_dy = g_postT[(size_t)(2*k  )*NPOS + pos];
        float my_dx = g_postT[(size_t)(2*k+1)*NPOS + pos];
        float my_m  = g_postT[(size_t)(18+k )*NPOS + pos];
        int ky = k / 3, kx = k % 3;

        // ---- sampling: warp covers positions warp*32 .. warp*32+31 ----
#pragma unroll 4
        for (int i = 0; i < 16; ++i) {
            int pl  = 2*i + sub;          // lane owning this position
            int spos = warp*32 + pl;
            float dy = __shfl_sync(0xffffffffu, my_dy, pl);
            float dx = __shfl_sync(0xffffffffu, my_dx, pl);
            float m  = __shfl_sync(0xffffffffu, my_m,  pl);

            float py = dy + (float)(ky + y    - 1);
            float px = dx + (float)(kx + spos - 1);
            float fy = floorf(py), fx = floorf(px);
            float wy1 = py - fy, wx1 = px - fx;
            float wy0 = 1.f - wy1, wx0 = 1.f - wx1;
            int y0 = (int)fy, x0 = (int)fx;
            int y1 = y0 + 1, x1 = x0 + 1;
            bool vy0 = (y0 >= 0) & (y0 < HH), vy1 = (y1 >= 0) & (y1 < HH);
            bool vx0 = (x0 >= 0) & (x0 < WW), vx1 = (x1 >= 0) & (x1 < WW);
            float w00 = (vy0 && vx0) ? wy0*wx0*m : 0.f;
            float w01 = (vy0 && vx1) ? wy0*wx1*m : 0.f;
            float w10 = (vy1 && vx0) ? wy1*wx0*m : 0.f;
            float w11 = (vy1 && vx1) ? wy1*wx1*m : 0.f;
            int yc0 = min(max(y0, 0), HH-1), yc1 = min(max(y1, 0), HH-1);
            int xc0 = min(max(x0, 0), WW-1), xc1 = min(max(x1, 0), WW-1);

            // 32-bit offsets; c4 term folded once
            int r0 = imgbase + yc0*(WW*CIN) + c4*4;
            int r1 = imgbase + yc1*(WW*CIN) + c4*4;
            float4 a  = *reinterpret_cast<const float4*>(g_xT + r0 + xc0*CIN);
            float4 bb = *reinterpret_cast<const float4*>(g_xT + r0 + xc1*CIN);
            float4 cv = *reinterpret_cast<const float4*>(g_xT + r1 + xc0*CIN);
            float4 d  = *reinterpret_cast<const float4*>(g_xT + r1 + xc1*CIN);

            float v0 = w00*a.x + w01*bb.x + w10*cv.x + w11*d.x;
            float v1 = w00*a.y + w01*bb.y + w10*cv.y + w11*d.y;
            float v2 = w00*a.z + w01*bb.z + w10*cv.z + w11*d.z;
            float v3 = w00*a.w + w01*bb.w + w10*cv.w + w11*d.w;

            int col = spos ^ (c4 << 1);   // XOR swizzle (bank-conflict-free)
            A_sh[c4*4+0][col] = v0;
            A_sh[c4*4+1][col] = v1;
            A_sh[c4*4+2][col] = v2;
            A_sh[c4*4+3][col] = v3;
        }

        __syncthreads();  // A + W ready

        // ---- GEMM: 64 c; per c: 6 LDS + 8 MOV + 32 FFMA2 ----
#pragma unroll 2
        for (int c = 0; c < 64; ++c) {
            const float4* wf = reinterpret_cast<const float4*>(&W_sh[c][og*8]);
            float4 wlo = wf[0], whi = wf[1];
            unsigned long long w0 = dup2(wlo.x), w1 = dup2(wlo.y);
            unsigned long long w2 = dup2(wlo.z), w3 = dup2(wlo.w);
            unsigned long long w4 = dup2(whi.x), w5 = dup2(whi.y);
            unsigned long long w6 = dup2(whi.z), w7 = dup2(whi.w);

            int cx = (pcol*2) ^ ((c >> 2) << 1);   // swizzled pair column
            const float* ar = &A_sh[c][0];
            unsigned long long a0 = *reinterpret_cast<const unsigned long long*>(ar + cx);
            unsigned long long a1 = *reinterpret_cast<const unsigned long long*>(ar + cx + 32);
            unsigned long long a2 = *reinterpret_cast<const unsigned long long*>(ar + cx + 64);
            unsigned long long a3 = *reinterpret_cast<const unsigned long long*>(ar + cx + 96);

            ffma2(acc[ 0], a0, w0); ffma2(acc[ 1], a0, w1);
            ffma2(acc[ 2], a0, w2); ffma2(acc[ 3], a0, w3);
            ffma2(acc[ 4], a0, w4); ffma2(acc[ 5], a0, w5);
            ffma2(acc[ 6], a0, w6); ffma2(acc[ 7], a0, w7);
            ffma2(acc[ 8], a1, w0); ffma2(acc[ 9], a1, w1);
            ffma2(acc[10], a1, w2); ffma2(acc[11], a1, w3);
            ffma2(acc[12], a1, w4); ffma2(acc[13], a1, w5);
            ffma2(acc[14], a1, w6); ffma2(acc[15], a1, w7);
            ffma2(acc[16], a2, w0); ffma2(acc[17], a2, w1);
            ffma2(acc[18], a2, w2); ffma2(acc[19], a2, w3);
            ffma2(acc[20], a2, w4); ffma2(acc[21], a2, w5);
            ffma2(acc[22], a2, w6); ffma2(acc[23], a2, w7);
            ffma2(acc[24], a3, w0); ffma2(acc[25], a3, w1);
            ffma2(acc[26], a3, w2); ffma2(acc[27], a3, w3);
            ffma2(acc[28], a3, w4); ffma2(acc[29], a3, w5);
            ffma2(acc[30], a3, w6); ffma2(acc[31], a3, w7);
        }
    }

    // ---- epilogue: packed 8-byte stores, coalesced per half-warp ----
#pragma unroll
    for (int j = 0; j < 8; ++j) {
        int o = og*8 + j;
        float* orow = out + (((size_t)(b*OUTC) + o)*HH + y) * WW;
#pragma unroll
        for (int i2 = 0; i2 < 4; ++i2)
            *reinterpret_cast<unsigned long long*>(orow + pcol*2 + i2*32) =
                acc[i2*8+j];
    }
}

// ---------------------------------------------------------------------------
extern "C" void kernel_launch(void* const* d_in, const int* in_sizes, int n_in,
                              void* d_out, int out_size) {
    const float* x   = (const float*)d_in[0];
    const float* ow  = (const float*)d_in[1];
    const float* ob  = (const float*)d_in[2];
    const float* mw  = (const float*)d_in[3];
    const float* mb  = (const float*)d_in[4];
    const float* dw  = (const float*)d_in[5];
    const float* db  = (const float*)d_in[6];
    float* out = (float*)d_out;

    kW<<<64, 256>>>(ow, mw, dw);
    kA<<<BATCH*HH, 128>>>(x);
    kF<<<BATCH*HH, 128>>>(x, ob, mb, db, out);
}

// round 16
// speedup vs baseline: 1.1850x; 1.1850x over previous
#include <cuda_runtime.h>
#include <cuda_bf16.h>

// Problem constants
#define BATCH 4
#define CIN   64
#define HH    128
#define WW    128
#define OUTC  64
#define K2N   9
#define NPOS  (BATCH*HH*WW)

// Scratch (device globals; no allocation allowed)
__device__ __align__(16) float g_xT[BATCH*HH*WW*CIN];   // [b][y][x][c]
__device__ __align__(16) float g_postT[28*NPOS];        // [j][pos] offsets/masks (transposed)
__device__ __align__(16) float g_cwT[9*64*28];          // [tap][c][j]
__device__ __align__(16) float g_dwT[9*64*64];          // [k][c][o]

// ------------------------- f32x2 helpers (sm_100+) -------------------------
__device__ __forceinline__ void ffma2(unsigned long long& d,
                                      unsigned long long a,
                                      unsigned long long b) {
    asm("fma.rn.f32x2 %0, %1, %2, %0;" : "+l"(d) : "l"(a), "l"(b));
}
__device__ __forceinline__ unsigned long long dup2(float a) {
    unsigned long long r;
    asm("mov.b64 %0, {%1, %1};" : "=l"(r) : "f"(a));
    return r;
}

// ---------------------------------------------------------------------------
// Kernel W: weight transposes (tiny)
// ---------------------------------------------------------------------------
__global__ void kW(const float* __restrict__ ow, const float* __restrict__ mw,
                   const float* __restrict__ dw) {
    int i = blockIdx.x * blockDim.x + threadIdx.x;
    int stride = gridDim.x * blockDim.x;
    for (int idx = i; idx < 9*64*28; idx += stride) {
        int j   = idx % 28;
        int c   = (idx / 28) % 64;
        int tap = idx / (28*64);
        float v = 0.f;
        if (j < 18)      v = ow[j*576 + c*9 + tap];
        else if (j < 27) v = mw[(j-18)*576 + c*9 + tap];
        g_cwT[idx] = v;
    }
    // g_dwT[k][c][o] = dw[o][c][k]
    for (int idx = i; idx < 9*64*64; idx += stride) {
        int o = idx & 63;
        int c = (idx >> 6) & 63;
        int k = idx >> 12;
        g_dwT[idx] = dw[o*576 + c*9 + k];
    }
}

// ---------------------------------------------------------------------------
// Kernel A: NCHW -> NHWC transpose of x  (grid = BATCH*HH, block = 128)
// ---------------------------------------------------------------------------
__global__ __launch_bounds__(128) void kA(const float* __restrict__ x) {
    int by = blockIdx.x;
    int b = by >> 7, y = by & 127;
    int xq = threadIdx.x;
    const float* src = x + ((size_t)(b*CIN)*HH + y) * WW + xq;
    float* dst = g_xT + (((size_t)b*HH + y) * WW + xq) * CIN;
#pragma unroll
    for (int c4 = 0; c4 < 16; ++c4) {
        float4 v;
        v.x = src[(size_t)(c4*4+0)*HH*WW];
        v.y = src[(size_t)(c4*4+1)*HH*WW];
        v.z = src[(size_t)(c4*4+2)*HH*WW];
        v.w = src[(size_t)(c4*4+3)*HH*WW];
        *reinterpret_cast<float4*>(dst + c4*4) = v;
    }
}

// ---------------------------------------------------------------------------
// Kernel F: FUSED offset/mask conv + bilinear sampling + deform GEMM.
// grid = BATCH*HH, block = 128 (NO min-blocks bound: 137 regs is fine).
// Smem: double-buffered A_sh[2][64][128] = 64KB. NO W_sh: the GEMM reads
//   weights straight from g_dwT with 16-lane-uniform broadcast LDG.128
//   (L1-hot 16KB slab per k). 3 blocks/SM by smem & regs.
// Pipeline: ONE sync per k — iter k samples (k+1) into A[(k+1)&1] and runs
//   GEMM k from A[k&1]; warps stalled in sampling overlap with warps in GEMM.
// ---------------------------------------------------------------------------
__global__ __launch_bounds__(128) void kF(const float* __restrict__ x,
                                          const float* __restrict__ ob,
                                          const float* __restrict__ mb,
                                          const float* __restrict__ db,
                                          float* __restrict__ out) {
    __shared__ __align__(16) float A_sh[2][64][128];   // 64 KB

    int by = blockIdx.x;
    int b = by >> 7, y = by & 127;
    int tid  = threadIdx.x;
    int lane = tid & 31;
    int warp = tid >> 5;
    size_t rowbase = ((size_t)(b*HH) + y) * WW;
    size_t pos = rowbase + tid;

    // ================= Phase 1: offset + mask conv =================
    {
        float* sw = &A_sh[1][0][0];   // scratch: 1792 floats of buffer 1
        unsigned long long bacc[14];
#pragma unroll
        for (int j = 0; j < 14; ++j) bacc[j] = 0ULL;

        for (int tap = 0; tap < 9; ++tap) {
            __syncthreads();
            for (int t = tid; t < 448; t += 128)
                reinterpret_cast<float4*>(sw)[t] =
                    reinterpret_cast<const float4*>(g_cwT + tap*1792)[t];
            __syncthreads();

            int ky = tap / 3, kx = tap % 3;
            int ys = y + ky - 1, xs = tid + kx - 1;
            if (ys < 0 || ys > 127 || xs < 0 || xs > 127) continue;  // zero pad

            const float* xc = x + ((size_t)(b*CIN)*HH + ys) * WW + xs;
#pragma unroll 4
            for (int c = 0; c < 64; ++c) {
                unsigned long long ad = dup2(xc[(size_t)c*HH*WW]);
                const float4* wp = reinterpret_cast<const float4*>(sw + c*28);
#pragma unroll
                for (int j4 = 0; j4 < 7; ++j4) {
                    float4 w = wp[j4];
                    const unsigned long long* wu =
                        reinterpret_cast<const unsigned long long*>(&w);
                    ffma2(bacc[j4*2+0], ad, wu[0]);
                    ffma2(bacc[j4*2+1], ad, wu[1]);
                }
            }
        }

        float r[28];
#pragma unroll
        for (int j2 = 0; j2 < 14; ++j2) {
            float2 f = *reinterpret_cast<float2*>(&bacc[j2]);
            r[2*j2+0] = f.x;
            r[2*j2+1] = f.y;
        }
#pragma unroll
        for (int j = 0; j < 18; ++j) r[j] += ob[j];
#pragma unroll
        for (int j = 0; j < 9; ++j) {
            float t = r[18+j] + mb[j];
            r[18+j] = 1.f / (1.f + __expf(-t));
        }
        // Each thread later reads back ONLY its own entries (self-visibility).
#pragma unroll
        for (int j = 0; j < 27; ++j)
            g_postT[(size_t)j*NPOS + pos] = r[j];
    }

    // ================= Phase 2: sampling + deform GEMM =================
    int pcol = tid & 15;     // GEMM: x pairs at pcol*2 + i2*32
    int og   = tid >> 4;     // GEMM: outputs o = og*8 + j
    int sub  = lane >> 4;    // sampling: position sub-slot (0/1)
    int c4   = lane & 15;    // sampling: channel quad

    unsigned long long acc[32];
#pragma unroll
    for (int j = 0; j < 8; ++j) {
        unsigned long long bd = dup2(db[og*8 + j]);
#pragma unroll
        for (int i2 = 0; i2 < 4; ++i2) acc[i2*8+j] = bd;
    }

    // --- sampling lambda-equivalent (macro-free, inlined twice) ---
    // Samples tap k into A_sh[buf]. Uses per-thread g_postT scalars + shfl.
#define SAMPLE_TAP(KK, BUF)                                                    \
    {                                                                          \
        int k_ = (KK);                                                         \
        float my_dy = g_postT[(size_t)(2*k_  )*NPOS + pos];                    \
        float my_dx = g_postT[(size_t)(2*k_+1)*NPOS + pos];                    \
        float my_m  = g_postT[(size_t)(18+k_ )*NPOS + pos];                    \
        int ky = k_ / 3, kx = k_ % 3;                                          \
        _Pragma("unroll 4")                                                    \
        for (int i = 0; i < 16; ++i) {                                         \
            int pl   = 2*i + sub;                                              \
            int spos = warp*32 + pl;                                           \
            float dy = __shfl_sync(0xffffffffu, my_dy, pl);                    \
            float dx = __shfl_sync(0xffffffffu, my_dx, pl);                    \
            float m  = __shfl_sync(0xffffffffu, my_m,  pl);                    \
            float py = dy + (float)(ky + y    - 1);                            \
            float px = dx + (float)(kx + spos - 1);                            \
            float fy = floorf(py), fx = floorf(px);                            \
            float wy1 = py - fy, wx1 = px - fx;                                \
            float wy0 = 1.f - wy1, wx0 = 1.f - wx1;                            \
            int y0 = (int)fy, x0 = (int)fx;                                    \
            int y1 = y0 + 1, x1 = x0 + 1;                                      \
            bool vy0 = (y0 >= 0) & (y0 < HH), vy1 = (y1 >= 0) & (y1 < HH);     \
            bool vx0 = (x0 >= 0) & (x0 < WW), vx1 = (x1 >= 0) & (x1 < WW);     \
            float w00 = (vy0 && vx0) ? wy0*wx0*m : 0.f;                        \
            float w01 = (vy0 && vx1) ? wy0*wx1*m : 0.f;                        \
            float w10 = (vy1 && vx0) ? wy1*wx0*m : 0.f;                        \
            float w11 = (vy1 && vx1) ? wy1*wx1*m : 0.f;                        \
            int yc0 = min(max(y0, 0), HH-1), yc1 = min(max(y1, 0), HH-1);      \
            int xc0 = min(max(x0, 0), WW-1), xc1 = min(max(x1, 0), WW-1);      \
            const float4* p00 = reinterpret_cast<const float4*>(g_xT + (((size_t)b*HH + yc0)*WW + xc0)*CIN); \
            const float4* p01 = reinterpret_cast<const float4*>(g_xT + (((size_t)b*HH + yc0)*WW + xc1)*CIN); \
            const float4* p10 = reinterpret_cast<const float4*>(g_xT + (((size_t)b*HH + yc1)*WW + xc0)*CIN); \
            const float4* p11 = reinterpret_cast<const float4*>(g_xT + (((size_t)b*HH + yc1)*WW + xc1)*CIN); \
            float4 a = p00[c4], bb = p01[c4], cv = p10[c4], d = p11[c4];       \
            float v0 = w00*a.x + w01*bb.x + w10*cv.x + w11*d.x;                \
            float v1 = w00*a.y + w01*bb.y + w10*cv.y + w11*d.y;                \
            float v2 = w00*a.z + w01*bb.z + w10*cv.z + w11*d.z;                \
            float v3 = w00*a.w + w01*bb.w + w10*cv.w + w11*d.w;                \
            int col = spos ^ (c4 << 1);                                        \
            A_sh[BUF][c4*4+0][col] = v0;                                       \
            A_sh[BUF][c4*4+1][col] = v1;                                       \
            A_sh[BUF][c4*4+2][col] = v2;                                       \
            A_sh[BUF][c4*4+3][col] = v3;                                       \
        }                                                                      \
    }

    // Prologue: sample k=0 into buffer 0 (buffer 1 was phase-1 scratch;
    // disjoint, no sync needed before this).
    SAMPLE_TAP(0, 0);
    __syncthreads();

    for (int k = 0; k < 9; ++k) {
        int buf  = k & 1;
        int nbuf = buf ^ 1;

        // ---- sample next tap into the other buffer (skipped on last k) ----
        if (k < 8) SAMPLE_TAP(k + 1, nbuf);

        // ---- GEMM k: W from g_dwT via broadcast LDG (L1-hot) ----
        const float* wbase = g_dwT + (size_t)k*4096 + og*8;
#pragma unroll 2
        for (int c = 0; c < 64; ++c) {
            const float4* wf = reinterpret_cast<const float4*>(wbase + c*64);
            float4 wlo = wf[0], whi = wf[1];
            unsigned long long w0 = dup2(wlo.x), w1 = dup2(wlo.y);
            unsigned long long w2 = dup2(wlo.z), w3 = dup2(wlo.w);
            unsigned long long w4 = dup2(whi.x), w5 = dup2(whi.y);
            unsigned long long w6 = dup2(whi.z), w7 = dup2(whi.w);

            int cx = (pcol*2) ^ ((c >> 2) << 1);   // swizzled pair column
            const float* ar = &A_sh[buf][c][0];
            unsigned long long a0 = *reinterpret_cast<const unsigned long long*>(ar + cx);
            unsigned long long a1 = *reinterpret_cast<const unsigned long long*>(ar + cx + 32);
            unsigned long long a2 = *reinterpret_cast<const unsigned long long*>(ar + cx + 64);
            unsigned long long a3 = *reinterpret_cast<const unsigned long long*>(ar + cx + 96);

            ffma2(acc[ 0], a0, w0); ffma2(acc[ 1], a0, w1);
            ffma2(acc[ 2], a0, w2); ffma2(acc[ 3], a0, w3);
            ffma2(acc[ 4], a0, w4); ffma2(acc[ 5], a0, w5);
            ffma2(acc[ 6], a0, w6); ffma2(acc[ 7], a0, w7);
            ffma2(acc[ 8], a1, w0); ffma2(acc[ 9], a1, w1);
            ffma2(acc[10], a1, w2); ffma2(acc[11], a1, w3);
            ffma2(acc[12], a1, w4); ffma2(acc[13], a1, w5);
            ffma2(acc[14], a1, w6); ffma2(acc[15], a1, w7);
            ffma2(acc[16], a2, w0); ffma2(acc[17], a2, w1);
            ffma2(acc[18], a2, w2); ffma2(acc[19], a2, w3);
            ffma2(acc[20], a2, w4); ffma2(acc[21], a2, w5);
            ffma2(acc[22], a2, w6); ffma2(acc[23], a2, w7);
            ffma2(acc[24], a3, w0); ffma2(acc[25], a3, w1);
            ffma2(acc[26], a3, w2); ffma2(acc[27], a3, w3);
            ffma2(acc[28], a3, w4); ffma2(acc[29], a3, w5);
            ffma2(acc[30], a3, w6); ffma2(acc[31], a3, w7);
        }

        // One sync per k: A[nbuf] writes done (next GEMM safe) AND all GEMM
        // reads of A[buf] done (next iteration may overwrite it).
        __syncthreads();
    }
#undef SAMPLE_TAP

    // ---- epilogue: packed 8-byte stores, coalesced per half-warp ----
#pragma unroll
    for (int j = 0; j < 8; ++j) {
        int o = og*8 + j;
        float* orow = out + (((size_t)(b*OUTC) + o)*HH + y) * WW;
#pragma unroll
        for (int i2 = 0; i2 < 4; ++i2)
            *reinterpret_cast<unsigned long long*>(orow + pcol*2 + i2*32) =
                acc[i2*8+j];
    }
}

// ---------------------------------------------------------------------------
extern "C" void kernel_launch(void* const* d_in, const int* in_sizes, int n_in,
                              void* d_out, int out_size) {
    const float* x   = (const float*)d_in[0];
    const float* ow  = (const float*)d_in[1];
    const float* ob  = (const float*)d_in[2];
    const float* mw  = (const float*)d_in[3];
    const float* mb  = (const float*)d_in[4];
    const float* dw  = (const float*)d_in[5];
    const float* db  = (const float*)d_in[6];
    float* out = (float*)d_out;

    kW<<<64, 256>>>(ow, mw, dw);
    kA<<<BATCH*HH, 128>>>(x);
    kF<<<BATCH*HH, 128>>>(x, ob, mb, db, out);
}

// round 17
// speedup vs baseline: 1.4040x; 1.1848x over previous
#include <cuda_runtime.h>
#include <cuda_bf16.h>

// Problem constants
#define BATCH 4
#define CIN   64
#define HH    128
#define WW    128
#define OUTC  64
#define K2N   9
#define NPOS  (BATCH*HH*WW)

// Scratch (device globals; no allocation allowed)
__device__ __align__(16) float g_xT[BATCH*HH*WW*CIN];   // [b][y][x][c]
__device__ __align__(16) float g_cwT[9*64*28];          // [tap][c][j]
__device__ __align__(16) float g_dwT[9*64*64];          // [k][c][o]

// ------------------------- f32x2 helpers (sm_100+) -------------------------
__device__ __forceinline__ void ffma2(unsigned long long& d,
                                      unsigned long long a,
                                      unsigned long long b) {
    asm("fma.rn.f32x2 %0, %1, %2, %0;" : "+l"(d) : "l"(a), "l"(b));
}
__device__ __forceinline__ unsigned long long dup2(float a) {
    unsigned long long r;
    asm("mov.b64 %0, {%1, %1};" : "=l"(r) : "f"(a));
    return r;
}

// ---------------------------------------------------------------------------
// Kernel W: weight transposes (tiny)
// ---------------------------------------------------------------------------
__global__ void kW(const float* __restrict__ ow, const float* __restrict__ mw,
                   const float* __restrict__ dw) {
    int i = blockIdx.x * blockDim.x + threadIdx.x;
    int stride = gridDim.x * blockDim.x;
    for (int idx = i; idx < 9*64*28; idx += stride) {
        int j   = idx % 28;
        int c   = (idx / 28) % 64;
        int tap = idx / (28*64);
        float v = 0.f;
        if (j < 18)      v = ow[j*576 + c*9 + tap];
        else if (j < 27) v = mw[(j-18)*576 + c*9 + tap];
        g_cwT[idx] = v;
    }
    // g_dwT[k][c][o] = dw[o][c][k]
    for (int idx = i; idx < 9*64*64; idx += stride) {
        int o = idx & 63;
        int c = (idx >> 6) & 63;
        int k = idx >> 12;
        g_dwT[idx] = dw[o*576 + c*9 + k];
    }
}

// ---------------------------------------------------------------------------
// Kernel A: NCHW -> NHWC transpose of x  (grid = BATCH*HH, block = 128)
// ---------------------------------------------------------------------------
__global__ __launch_bounds__(128) void kA(const float* __restrict__ x) {
    int by = blockIdx.x;
    int b = by >> 7, y = by & 127;
    int xq = threadIdx.x;
    const float* src = x + ((size_t)(b*CIN)*HH + y) * WW + xq;
    float* dst = g_xT + (((size_t)b*HH + y) * WW + xq) * CIN;
#pragma unroll
    for (int c4 = 0; c4 < 16; ++c4) {
        float4 v;
        v.x = src[(size_t)(c4*4+0)*HH*WW];
        v.y = src[(size_t)(c4*4+1)*HH*WW];
        v.z = src[(size_t)(c4*4+2)*HH*WW];
        v.w = src[(size_t)(c4*4+3)*HH*WW];
        *reinterpret_cast<float4*>(dst + c4*4) = v;
    }
}

// ---------------------------------------------------------------------------
// Kernel F: FUSED offset/mask conv + bilinear sampling + deform GEMM.
// grid = BATCH*HH (one (b,y) row per block), block = 128.
// Smem: A_sh [64][128] (32KB) + W_sh [64][64] (16KB) + off_sh [27][128]
//   (13.5KB) = 62.9KB -> 3 blocks/SM (regs limit to 3 anyway).
// Phase 1 (row-staged): for each of 3 input rows, stage [64c][128x] in A_sh
//   (coalesced LDG once), then 3 taps read cheap LDS.32. Weights per tap in
//   W_sh. Results (18 offsets + 9 sigmoid masks) -> off_sh via STS.
// Phase 2: identical GEMM to the 246us R12 kernel; sampling reads its
//   per-position scalars from off_sh with broadcast LDS (no shfl, no gmem).
// ---------------------------------------------------------------------------
__global__ __launch_bounds__(128) void kF(const float* __restrict__ x,
                                          const float* __restrict__ ob,
                                          const float* __restrict__ mb,
                                          const float* __restrict__ db,
                                          float* __restrict__ out) {
    __shared__ __align__(16) float A_sh[64][128];
    __shared__ __align__(16) float W_sh[64][64];    // phase2 [c][o]; phase1 tap weights
    __shared__ __align__(16) float off_sh[27][128]; // [j][pos]

    int by = blockIdx.x;
    int b = by >> 7, y = by & 127;
    int tid  = threadIdx.x;
    int lane = tid & 31;
    int warp = tid >> 5;

    // ================= Phase 1: offset + mask conv (row-staged) ==========
    {
        float* sw = &W_sh[0][0];   // 1792 floats used of 4096
        unsigned long long bacc[14];
#pragma unroll
        for (int j = 0; j < 14; ++j) bacc[j] = 0ULL;

        for (int r3 = 0; r3 < 3; ++r3) {
            int ys = y + r3 - 1;
            bool rowok = (ys >= 0) && (ys < HH);

            __syncthreads();   // A_sh free (prev taps done reading)
            if (rowok) {
                const float* xc = x + ((size_t)(b*CIN)*HH + ys) * WW + tid;
#pragma unroll 8
                for (int c = 0; c < 64; ++c)
                    A_sh[c][tid] = xc[(size_t)c*HH*WW];
            }

            for (int kx = 0; kx < 3; ++kx) {
                int tap = r3*3 + kx;
                __syncthreads();   // staging visible; prev weights done
                for (int t = tid; t < 448; t += 128)
                    reinterpret_cast<float4*>(sw)[t] =
                        reinterpret_cast<const float4*>(g_cwT + tap*1792)[t];
                __syncthreads();   // weights ready

                int xs = tid + kx - 1;
                if (!rowok || xs < 0 || xs > 127) continue;   // zero pad

#pragma unroll 8
                for (int c = 0; c < 64; ++c) {
                    unsigned long long ad = dup2(A_sh[c][xs]);   // LDS.32
                    const float4* wp = reinterpret_cast<const float4*>(sw + c*28);
#pragma unroll
                    for (int j4 = 0; j4 < 7; ++j4) {
                        float4 w = wp[j4];
                        const unsigned long long* wu =
                            reinterpret_cast<const unsigned long long*>(&w);
                        ffma2(bacc[j4*2+0], ad, wu[0]);
                        ffma2(bacc[j4*2+1], ad, wu[1]);
                    }
                }
            }
        }

        float r[28];
#pragma unroll
        for (int j2 = 0; j2 < 14; ++j2) {
            float2 f = *reinterpret_cast<float2*>(&bacc[j2]);
            r[2*j2+0] = f.x;
            r[2*j2+1] = f.y;
        }
#pragma unroll
        for (int j = 0; j < 18; ++j) r[j] += ob[j];
#pragma unroll
        for (int j = 0; j < 9; ++j) {
            float t = r[18+j] + mb[j];
            r[18+j] = 1.f / (1.f + __expf(-t));
        }
#pragma unroll
        for (int j = 0; j < 27; ++j)
            off_sh[j][tid] = r[j];
        // visible block-wide after the __syncthreads() in the k-loop below.
    }

    // ================= Phase 2: sampling + deform GEMM =================
    int pcol = tid & 15;     // GEMM: x pairs at pcol*2 + i2*32
    int og   = tid >> 4;     // GEMM: outputs o = og*8 + j
    int sub  = lane >> 4;    // sampling: position sub-slot (0/1)
    int c4   = lane & 15;    // sampling: channel quad

    unsigned long long acc[32];
#pragma unroll
    for (int j = 0; j < 8; ++j) {
        unsigned long long bd = dup2(db[og*8 + j]);
#pragma unroll
        for (int i2 = 0; i2 < 4; ++i2) acc[i2*8+j] = bd;
    }

    for (int k = 0; k < 9; ++k) {
        __syncthreads();  // prev GEMM done reading A/W; off_sh visible (k=0)

        // ---- fill W slab for this k: 1024 float4, 8 per thread ----
        {
            const float4* src = reinterpret_cast<const float4*>(g_dwT + (size_t)k*4096);
            float4* dst = reinterpret_cast<float4*>(&W_sh[0][0]);
#pragma unroll
            for (int t = 0; t < 8; ++t)
                dst[tid + t*128] = src[tid + t*128];
        }

        int ky = k / 3, kx = k % 3;

        // ---- sampling: warp covers positions warp*32 .. warp*32+31 ----
#pragma unroll 4
        for (int i = 0; i < 16; ++i) {
            int pl   = 2*i + sub;          // position slot within warp
            int spos = warp*32 + pl;
            float dy = off_sh[2*k  ][spos];   // broadcast LDS
            float dx = off_sh[2*k+1][spos];
            float m  = off_sh[18+k ][spos];

            float py = dy + (float)(ky + y    - 1);
            float px = dx + (float)(kx + spos - 1);
            float fy = floorf(py), fx = floorf(px);
            float wy1 = py - fy, wx1 = px - fx;
            float wy0 = 1.f - wy1, wx0 = 1.f - wx1;
            int y0 = (int)fy, x0 = (int)fx;
            int y1 = y0 + 1, x1 = x0 + 1;
            bool vy0 = (y0 >= 0) & (y0 < HH), vy1 = (y1 >= 0) & (y1 < HH);
            bool vx0 = (x0 >= 0) & (x0 < WW), vx1 = (x1 >= 0) & (x1 < WW);
            float w00 = (vy0 && vx0) ? wy0*wx0*m : 0.f;
            float w01 = (vy0 && vx1) ? wy0*wx1*m : 0.f;
            float w10 = (vy1 && vx0) ? wy1*wx0*m : 0.f;
            float w11 = (vy1 && vx1) ? wy1*wx1*m : 0.f;
            int yc0 = min(max(y0, 0), HH-1), yc1 = min(max(y1, 0), HH-1);
            int xc0 = min(max(x0, 0), WW-1), xc1 = min(max(x1, 0), WW-1);

            const float4* p00 = reinterpret_cast<const float4*>(g_xT + (((size_t)b*HH + yc0)*WW + xc0)*CIN);
            const float4* p01 = reinterpret_cast<const float4*>(g_xT + (((size_t)b*HH + yc0)*WW + xc1)*CIN);
            const float4* p10 = reinterpret_cast<const float4*>(g_xT + (((size_t)b*HH + yc1)*WW + xc0)*CIN);
            const float4* p11 = reinterpret_cast<const float4*>(g_xT + (((size_t)b*HH + yc1)*WW + xc1)*CIN);

            float4 a = p00[c4], bb = p01[c4], cv = p10[c4], d = p11[c4];
            float v0 = w00*a.x + w01*bb.x + w10*cv.x + w11*d.x;
            float v1 = w00*a.y + w01*bb.y + w10*cv.y + w11*d.y;
            float v2 = w00*a.z + w01*bb.z + w10*cv.z + w11*d.z;
            float v3 = w00*a.w + w01*bb.w + w10*cv.w + w11*d.w;

            int col = spos ^ (c4 << 1);   // XOR swizzle (bank-conflict-free)
            A_sh[c4*4+0][col] = v0;
            A_sh[c4*4+1][col] = v1;
            A_sh[c4*4+2][col] = v2;
            A_sh[c4*4+3][col] = v3;
        }

        __syncthreads();  // A + W ready

        // ---- GEMM: 64 c; per c: 6 LDS + 8 MOV + 32 FFMA2 (R12-identical) ----
#pragma unroll 2
        for (int c = 0; c < 64; ++c) {
            const float4* wf = reinterpret_cast<const float4*>(&W_sh[c][og*8]);
            float4 wlo = wf[0], whi = wf[1];
            unsigned long long w0 = dup2(wlo.x), w1 = dup2(wlo.y);
            unsigned long long w2 = dup2(wlo.z), w3 = dup2(wlo.w);
            unsigned long long w4 = dup2(whi.x), w5 = dup2(whi.y);
            unsigned long long w6 = dup2(whi.z), w7 = dup2(whi.w);

            int cx = (pcol*2) ^ ((c >> 2) << 1);   // swizzled pair column
            const float* ar = &A_sh[c][0];
            unsigned long long a0 = *reinterpret_cast<const unsigned long long*>(ar + cx);
            unsigned long long a1 = *reinterpret_cast<const unsigned long long*>(ar + cx + 32);
            unsigned long long a2 = *reinterpret_cast<const unsigned long long*>(ar + cx + 64);
            unsigned long long a3 = *reinterpret_cast<const unsigned long long*>(ar + cx + 96);

            ffma2(acc[ 0], a0, w0); ffma2(acc[ 1], a0, w1);
            ffma2(acc[ 2], a0, w2); ffma2(acc[ 3], a0, w3);
            ffma2(acc[ 4], a0, w4); ffma2(acc[ 5], a0, w5);
            ffma2(acc[ 6], a0, w6); ffma2(acc[ 7], a0, w7);
            ffma2(acc[ 8], a1, w0); ffma2(acc[ 9], a1, w1);
            ffma2(acc[10], a1, w2); ffma2(acc[11], a1, w3);
            ffma2(acc[12], a1, w4); ffma2(acc[13], a1, w5);
            ffma2(acc[14], a1, w6); ffma2(acc[15], a1, w7);
            ffma2(acc[16], a2, w0); ffma2(acc[17], a2, w1);
            ffma2(acc[18], a2, w2); ffma2(acc[19], a2, w3);
            ffma2(acc[20], a2, w4); ffma2(acc[21], a2, w5);
            ffma2(acc[22], a2, w6); ffma2(acc[23], a2, w7);
            ffma2(acc[24], a3, w0); ffma2(acc[25], a3, w1);
            ffma2(acc[26], a3, w2); ffma2(acc[27], a3, w3);
            ffma2(acc[28], a3, w4); ffma2(acc[29], a3, w5);
            ffma2(acc[30], a3, w6); ffma2(acc[31], a3, w7);
        }
    }

    // ---- epilogue: packed 8-byte stores, coalesced per half-warp ----
#pragma unroll
    for (int j = 0; j < 8; ++j) {
        int o = og*8 + j;
        float* orow = out + (((size_t)(b*OUTC) + o)*HH + y) * WW;
#pragma unroll
        for (int i2 = 0; i2 < 4; ++i2)
            *reinterpret_cast<unsigned long long*>(orow + pcol*2 + i2*32) =
                acc[i2*8+j];
    }
}

// ---------------------------------------------------------------------------
extern "C" void kernel_launch(void* const* d_in, const int* in_sizes, int n_in,
                              void* d_out, int out_size) {
    const float* x   = (const float*)d_in[0];
    const float* ow  = (const float*)d_in[1];
    const float* ob  = (const float*)d_in[2];
    const float* mw  = (const float*)d_in[3];
    const float* mb  = (const float*)d_in[4];
    const float* dw  = (const float*)d_in[5];
    const float* db  = (const float*)d_in[6];
    float* out = (float*)d_out;

    kW<<<64, 256>>>(ow, mw, dw);
    kA<<<BATCH*HH, 128>>>(x);
    kF<<<BATCH*HH, 128>>>(x, ob, mb, db, out);
}